// round 2
// baseline (speedup 1.0000x reference)
#include <cuda_runtime.h>
#include <math.h>
#include <float.h>
#include <stdint.h>

#define VOCAB 32000
#define HID   1024
#define BEAM  16
#define TSTEPS 16
#define KS2   4    // gemm2 k-splits
#define KS1   16   // gemm1 k-splits

// ---------------- scratch (device globals; no allocation) ----------------
__device__ float g_lpart[KS2][BEAM][VOCAB];      // gemm2 partial logits (8 MB)
__device__ float g_stateA[BEAM][HID];
__device__ float g_stateB[BEAM][HID];
__device__ float g_p1ih[KS1][BEAM][HID];         // gemm1 partials (embed @ W_ih)
__device__ float g_p1hh[KS1][BEAM][HID];         // gemm1 partials (state @ W_hh)
__device__ float g_topval[BEAM][BEAM];           // per-beam top16 logprobs (sorted desc)
__device__ int   g_topidx[BEAM][BEAM];
__device__ float g_beam_lps[BEAM];
__device__ int   g_beam_seq[TSTEPS][BEAM];
__device__ float g_beam_seq_lp[TSTEPS][BEAM];
__device__ int   g_sel_c[BEAM];
__device__ int   g_sel_q[BEAM];

// ---------------- helpers ----------------
__device__ __forceinline__ bool better(float va, int ia, float vb, int ib) {
    // jax.lax.top_k order: larger value first; ties -> smaller index
    return (va > vb) || (va == vb && ia < ib);
}

__device__ __forceinline__ unsigned long long pack2(float x, float y) {
    unsigned long long r;
    asm("mov.b64 %0, {%1, %2};" : "=l"(r)
        : "r"(__float_as_uint(x)), "r"(__float_as_uint(y)));
    return r;
}
__device__ __forceinline__ void unpack2(unsigned long long v, float &x, float &y) {
    unsigned int a, b;
    asm("mov.b64 {%0, %1}, %2;" : "=r"(a), "=r"(b) : "l"(v));
    x = __uint_as_float(a); y = __uint_as_float(b);
}
__device__ __forceinline__ void fma2(unsigned long long &d, unsigned long long a,
                                     unsigned long long b) {
    asm("fma.rn.f32x2 %0, %1, %2, %3;" : "=l"(d) : "l"(a), "l"(b), "l"(d));
}

// ---------------- init ----------------
__global__ void init_kernel(const float* __restrict__ state) {
    int i = blockIdx.x * 256 + threadIdx.x;
    if (i < BEAM * HID) ((float*)g_stateA)[i] = state[i];
    if (i < BEAM) g_beam_lps[i] = 0.f;
}

// ---------------- fused (partial-sum) + logsumexp + per-beam top16 ----------------
__global__ void __launch_bounds__(256) topk_kernel(const float* __restrict__ logprobs0, int t) {
    __shared__ float sv[256][16];
    __shared__ int   si[256][16];
    __shared__ float rm[256], rs[256];
    int b = blockIdx.x, tid = threadIdx.x;

    float lv[16]; int li[16];
#pragma unroll
    for (int j = 0; j < 16; j++) { lv[j] = -INFINITY; li[j] = 0x7fffffff; }
    float m = -INFINITY, s = 0.f;

    for (int i = tid; i < VOCAB; i += 256) {
        float x;
        if (t == 0) {
            x = logprobs0[(size_t)b * VOCAB + i];
        } else {
            x = g_lpart[0][b][i] + g_lpart[1][b][i] + g_lpart[2][b][i] + g_lpart[3][b][i];
        }
        // online logsumexp over raw logits (only used for t>0)
        if (x > m) { s = s * __expf(m - x) + 1.f; m = x; }
        else       { s += __expf(x - m); }
        float v = (i == VOCAB - 1) ? x - 1000.f : x;  // lpf tweak (compare key)
        if (better(v, i, lv[15], li[15])) {
            // branchless shifted insert (all static indices -> registers)
#pragma unroll
            for (int j = 15; j >= 1; j--) {
                bool cj  = better(v, i, lv[j],     li[j]);
                bool cjm = better(v, i, lv[j - 1], li[j - 1]);
                float nv = cjm ? lv[j - 1] : v;
                int   ni = cjm ? li[j - 1] : i;
                lv[j] = cj ? nv : lv[j];
                li[j] = cj ? ni : li[j];
            }
            bool c0 = better(v, i, lv[0], li[0]);
            if (c0) { lv[0] = v; li[0] = i; }
        }
    }
#pragma unroll
    for (int j = 0; j < 16; j++) { sv[tid][j] = lv[j]; si[tid][j] = li[j]; }
    rm[tid] = m; rs[tid] = s;
    __syncthreads();

    for (int stride = 128; stride >= 1; stride >>= 1) {
        if (tid < stride) {
            // merge sorted lists tid and tid+stride -> top16 in registers
            float ov[16]; int oi[16];
            int pa = 0, pb = 0;
#pragma unroll
            for (int j = 0; j < 16; j++) {
                float av = sv[tid][pa];          int ai = si[tid][pa];
                float bv = sv[tid + stride][pb]; int bi = si[tid + stride][pb];
                bool ta = better(av, ai, bv, bi);
                ov[j] = ta ? av : bv; oi[j] = ta ? ai : bi;
                pa += ta; pb += !ta;
            }
#pragma unroll
            for (int j = 0; j < 16; j++) { sv[tid][j] = ov[j]; si[tid][j] = oi[j]; }
            // combine logsumexp
            float m2 = rm[tid + stride], s2 = rs[tid + stride];
            float m1 = rm[tid], s1 = rs[tid];
            float M = fmaxf(m1, m2);
            rs[tid] = s1 * __expf(m1 - M) + s2 * __expf(m2 - M);
            rm[tid] = M;
        }
        __syncthreads();
    }
    if (tid < 16) {
        float lvv = sv[0][tid];
        int   lii = si[0][tid];
        float outv;
        if (t == 0) {
            // reference uses input logprobs unmodified (already log_softmax'd);
            // store the compare key directly (bitwise-exact vs jax lpf values)
            outv = lvv;
        } else {
            // match reference rounding structure: lp = (x - max) - log(sum exp(x - max)),
            // then lpf applies -1000 at the last vocab slot AFTER normalization
            float mm  = rm[0];
            float lse = logf(rs[0]);
            if (lii == VOCAB - 1) {
                float x = g_lpart[0][b][lii] + g_lpart[1][b][lii]
                        + g_lpart[2][b][lii] + g_lpart[3][b][lii];
                outv = ((x - mm) - lse) - 1000.f;
            } else {
                outv = (lvv - mm) - lse;
            }
        }
        g_topval[b][tid] = outv;
        g_topidx[b][tid] = lii;
    }
}

// ---------------- global select among 256 candidates ----------------
__global__ void __launch_bounds__(256) select_kernel(int t) {
    __shared__ float cand[256];
    __shared__ float selv[16];
    __shared__ int   seli[16];
    __shared__ int   q_s[16], c_s[16];
    __shared__ float r_s[16], p_s[16];
    __shared__ int   oldseq[TSTEPS * BEAM];
    __shared__ float oldlp[TSTEPS * BEAM];
    int tid = threadIdx.x;
    int qi = tid >> 4, j = tid & 15;

    float cp = g_beam_lps[qi] + g_topval[qi][j];
    if (t == 0 && qi != 0) cp = -INFINITY;
    cand[tid] = cp;
    for (int idx = tid; idx < t * BEAM; idx += 256) {
        oldseq[idx] = ((const int*)g_beam_seq)[idx];
        oldlp[idx]  = ((const float*)g_beam_seq_lp)[idx];
    }
    __syncthreads();

    if (tid < 32) {
        for (int r = 0; r < 16; r++) {
            float bv = -INFINITY; int bi = 0x7fffffff;
#pragma unroll
            for (int k2 = 0; k2 < 8; k2++) {
                int idx = tid * 8 + k2;
                float v = cand[idx];
                if (better(v, idx, bv, bi)) { bv = v; bi = idx; }
            }
#pragma unroll
            for (int off = 16; off >= 1; off >>= 1) {
                float ov = __shfl_down_sync(0xffffffffu, bv, off);
                int   oi = __shfl_down_sync(0xffffffffu, bi, off);
                if (better(ov, oi, bv, bi)) { bv = ov; bi = oi; }
            }
            bv = __shfl_sync(0xffffffffu, bv, 0);
            bi = __shfl_sync(0xffffffffu, bi, 0);
            if (tid == 0) { selv[r] = bv; seli[r] = bi; cand[bi] = -INFINITY; }
            __syncwarp();
        }
        if (tid < 16) {
            int fi = seli[tid];
            int q = fi >> 4, col = fi & 15;
            int c = g_topidx[q][col];
            float rr = g_topval[q][col];
            q_s[tid] = q; c_s[tid] = c; r_s[tid] = rr;
            bool done = (c == 0) || (t == TSTEPS - 1);
            p_s[tid] = done ? -1000.f : selv[tid];
        }
    }
    __syncthreads();

    for (int idx = tid; idx < t * BEAM; idx += 256) {
        int row = idx >> 4, col = idx & 15;
        ((int*)g_beam_seq)[idx]      = oldseq[row * 16 + q_s[col]];
        ((float*)g_beam_seq_lp)[idx] = oldlp[row * 16 + q_s[col]];
    }
    if (tid < 16) {
        g_beam_seq[t][tid]    = c_s[tid];
        g_beam_seq_lp[t][tid] = r_s[tid];
        g_beam_lps[tid]       = p_s[tid];
        g_sel_c[tid] = c_s[tid];
        g_sel_q[tid] = q_s[tid];
    }
}

// ---------------- RNN cell GEMM (partials, separate ih/hh accumulators) ----------------
__global__ void __launch_bounds__(128) gemm1_kernel(const float* __restrict__ embed,
                                                    const float* __restrict__ Wih,
                                                    const float* __restrict__ Whh, int t) {
    const float (*state)[HID] = (t & 1) ? g_stateB : g_stateA;
    int cb = blockIdx.x;   // 0..7 (128 output cols each)
    int ks = blockIdx.y;   // 0..15 (64 k each)
    int tid = threadIdx.x;
    int o = cb * 128 + tid;
    __shared__ float xe[BEAM][64], xs[BEAM][64];
    for (int idx = tid; idx < BEAM * 64; idx += 128) {
        int bb = idx >> 6, kk = idx & 63;
        int k = ks * 64 + kk;
        xe[bb][kk] = embed[(size_t)g_sel_c[bb] * HID + k];
        xs[bb][kk] = state[g_sel_q[bb]][k];
    }
    __syncthreads();
    float aih[BEAM], ahh[BEAM];
#pragma unroll
    for (int bb = 0; bb < BEAM; bb++) { aih[bb] = 0.f; ahh[bb] = 0.f; }
#pragma unroll 4
    for (int kk = 0; kk < 64; kk++) {
        int k = ks * 64 + kk;
        float wih = Wih[(size_t)k * HID + o];
        float whh = Whh[(size_t)k * HID + o];
#pragma unroll
        for (int bb = 0; bb < BEAM; bb++) {
            aih[bb] += xe[bb][kk] * wih;
            ahh[bb] += xs[bb][kk] * whh;
        }
    }
#pragma unroll
    for (int bb = 0; bb < BEAM; bb++) {
        g_p1ih[ks][bb][o] = aih[bb];
        g_p1hh[ks][bb][o] = ahh[bb];
    }
}

__global__ void reduce_tanh_kernel(const float* __restrict__ bias, int t) {
    float (*out)[HID] = (t & 1) ? g_stateA : g_stateB;
    int i = blockIdx.x * 256 + threadIdx.x;   // 16384 total
    int bb = i >> 10, o = i & 1023;
    float sih = 0.f, shh = 0.f;
#pragma unroll
    for (int ks = 0; ks < KS1; ks++) { sih += g_p1ih[ks][bb][o]; shh += g_p1hh[ks][bb][o]; }
    float pre = (sih + shh) + bias[o];        // matches reference (d1 + d2) + b association
    out[bb][o] = (float)tanh((double)pre);    // double tanh: immune to fast-math MUFU.TANH
}

// ---------------- output projection (dominant kernel) ----------------
// grid (125, 4): 125 col-blocks (256 cols, 2/thread) x 4 k-splits (256 k each)
__global__ void __launch_bounds__(128) gemm2_kernel(const float* __restrict__ Wout, int t) {
    const float (*h)[HID] = (t & 1) ? g_stateA : g_stateB;
    int cb = blockIdx.x, ks = blockIdx.y;
    int tid = threadIdx.x;
    int col = cb * 256 + tid * 2;
    __shared__ float sh[256][18];   // [k][beam], padded
    for (int idx = tid; idx < BEAM * 256; idx += 128) {
        int bb = idx >> 8, kk = idx & 255;
        sh[kk][bb] = h[bb][ks * 256 + kk];
    }
    __syncthreads();
    unsigned long long acc0[8], acc1[8];
#pragma unroll
    for (int p = 0; p < 8; p++) { acc0[p] = 0ull; acc1[p] = 0ull; }
    const float* wp = Wout + (size_t)(ks * 256) * VOCAB + col;
#pragma unroll 8
    for (int kk = 0; kk < 256; kk++) {
        float2 w = *(const float2*)wp; wp += VOCAB;
        unsigned long long w0 = pack2(w.x, w.x);
        unsigned long long w1 = pack2(w.y, w.y);
#pragma unroll
        for (int p = 0; p < 8; p++) {
            unsigned long long x = *(const unsigned long long*)&sh[kk][2 * p];
            fma2(acc0[p], x, w0);
            fma2(acc1[p], x, w1);
        }
    }
#pragma unroll
    for (int p = 0; p < 8; p++) {
        float a, b2;
        unpack2(acc0[p], a, b2);
        g_lpart[ks][2 * p][col]     = a;
        g_lpart[ks][2 * p + 1][col] = b2;
        unpack2(acc1[p], a, b2);
        g_lpart[ks][2 * p][col + 1]     = a;
        g_lpart[ks][2 * p + 1][col + 1] = b2;
    }
}

// ---------------- pack outputs ----------------
__global__ void output_kernel(float* __restrict__ out, int out_size) {
    int i = blockIdx.x * 256 + threadIdx.x;
    if (i >= out_size) return;
    if (i < TSTEPS * BEAM) {
        out[i] = (float)((const int*)g_beam_seq)[i];
    } else if (i < 2 * TSTEPS * BEAM) {
        out[i] = ((const float*)g_beam_seq_lp)[i - TSTEPS * BEAM];
    } else if (i < 2 * TSTEPS * BEAM + BEAM) {
        out[i] = g_beam_lps[i - 2 * TSTEPS * BEAM];
    } else {
        out[i] = 0.f;
    }
}

extern "C" void kernel_launch(void* const* d_in, const int* in_sizes, int n_in,
                              void* d_out, int out_size) {
    const float* state    = (const float*)d_in[0];
    const float* logprobs = (const float*)d_in[1];
    const float* embed    = (const float*)d_in[2];
    const float* W_ih     = (const float*)d_in[3];
    const float* W_hh     = (const float*)d_in[4];
    const float* b        = (const float*)d_in[5];
    const float* W_out    = (const float*)d_in[6];

    init_kernel<<<64, 256>>>(state);
    for (int t = 0; t < TSTEPS; t++) {
        topk_kernel<<<BEAM, 256>>>(logprobs, t);
        select_kernel<<<1, 256>>>(t);
        if (t < TSTEPS - 1) {
            dim3 g1(8, KS1);
            gemm1_kernel<<<g1, 128>>>(embed, W_ih, W_hh, t);
            reduce_tanh_kernel<<<64, 256>>>(b, t);
            dim3 g2(125, KS2);
            gemm2_kernel<<<g2, 128>>>(W_out, t);
        }
    }
    int nblk = (out_size + 255) / 256;
    if (nblk < 1) nblk = 1;
    output_kernel<<<nblk, 256>>>((float*)d_out, out_size);
}

// round 3
// speedup vs baseline: 2.4490x; 2.4490x over previous
#include <cuda_runtime.h>
#include <math.h>
#include <float.h>
#include <stdint.h>

#define VOCAB 32000
#define HID   1024
#define BEAM  16
#define TSTEPS 16
#define KS2   8     // gemm2 k-splits (k=128 each)
#define KS1   64    // gemm1 k-splits over concatenated K=2048 (32 k each)
#define NCHUNK 8    // topk scan chunks per beam
#define CHSZ  4000  // VOCAB / NCHUNK

// ---------------- scratch (device globals; no allocation) ----------------
__device__ float g_lpart[KS2][BEAM][VOCAB];      // gemm2 partial logits (16 MB)
__device__ float g_stateA[BEAM][HID];
__device__ float g_stateB[BEAM][HID];
__device__ float g_part1[KS1][BEAM][HID];        // gemm1 partials (4 MB)
__device__ float g_cv[BEAM][NCHUNK][16];         // per-chunk top16 values (compare keys)
__device__ int   g_ci[BEAM][NCHUNK][16];
__device__ float g_cm[BEAM][NCHUNK];             // per-chunk lse max
__device__ float g_cs[BEAM][NCHUNK];             // per-chunk lse sum
__device__ float g_lastx[BEAM];                  // raw logit at vocab-1 (for exact tweak)
__device__ float g_beam_lps[BEAM];
__device__ int   g_beam_seq[TSTEPS][BEAM];
__device__ float g_beam_seq_lp[TSTEPS][BEAM];
__device__ int   g_sel_c[BEAM];
__device__ int   g_sel_q[BEAM];

// ---------------- helpers ----------------
__device__ __forceinline__ bool better(float va, int ia, float vb, int ib) {
    // jax.lax.top_k order: larger value first; ties -> smaller index
    return (va > vb) || (va == vb && ia < ib);
}

__device__ __forceinline__ unsigned long long pack2(float x, float y) {
    unsigned long long r;
    asm("mov.b64 %0, {%1, %2};" : "=l"(r)
        : "r"(__float_as_uint(x)), "r"(__float_as_uint(y)));
    return r;
}
__device__ __forceinline__ void unpack2(unsigned long long v, float &x, float &y) {
    unsigned int a, b;
    asm("mov.b64 {%0, %1}, %2;" : "=r"(a), "=r"(b) : "l"(v));
    x = __uint_as_float(a); y = __uint_as_float(b);
}
__device__ __forceinline__ void fma2(unsigned long long &d, unsigned long long a,
                                     unsigned long long b) {
    asm("fma.rn.f32x2 %0, %1, %2, %3;" : "=l"(d) : "l"(a), "l"(b), "l"(d));
}

// accurate fp32 tanh immune to fast-math MUFU.TANH (EX2-based, abs err ~1e-7)
__device__ __forceinline__ float tanh_acc(float x) {
    float ax = fabsf(x);
    float e  = __expf(2.0f * ax);          // e >= 1; e==inf -> r==1 (no NaN)
    float r  = 1.0f - 2.0f / (e + 1.0f);
    return copysignf(r, x);
}

// merge two sorted-desc 16-lists -> top16 (sequential, by one thread)
__device__ __forceinline__ void merge16(const float* av, const int* ai,
                                        const float* bv, const int* bi,
                                        float* ov, int* oi) {
    int pa = 0, pb = 0;
#pragma unroll
    for (int k = 0; k < 16; k++) {
        float x1 = av[pa]; int i1 = ai[pa];
        float x2 = bv[pb]; int i2 = bi[pb];
        bool ta = better(x1, i1, x2, i2);
        ov[k] = ta ? x1 : x2; oi[k] = ta ? i1 : i2;
        pa += ta; pb += !ta;
    }
}

// ---------------- init ----------------
__global__ void init_kernel(const float* __restrict__ state) {
    int i = blockIdx.x * 256 + threadIdx.x;
    if (i < BEAM * HID) ((float*)g_stateA)[i] = state[i];
    if (i < BEAM) g_beam_lps[i] = 0.f;
}

// ---------------- stage A: chunked scan (partial-sum + lse + top16) ----------------
// grid (NCHUNK, BEAM) x 256
__global__ void __launch_bounds__(256) topk_scan(const float* __restrict__ logprobs0, int t) {
    __shared__ float sv[256][16];
    __shared__ int   si[256][16];
    __shared__ float rm[256], rs[256];
    int chunk = blockIdx.x, b = blockIdx.y, tid = threadIdx.x;
    int base = chunk * CHSZ, end = base + CHSZ;

    float lv[16]; int li[16];
#pragma unroll
    for (int j = 0; j < 16; j++) { lv[j] = -INFINITY; li[j] = 0x7fffffff; }
    float m = -INFINITY, s = 0.f;

    for (int i = base + tid; i < end; i += 256) {
        float x;
        if (t == 0) {
            x = logprobs0[(size_t)b * VOCAB + i];
        } else {
            x = 0.f;
#pragma unroll
            for (int ks = 0; ks < KS2; ks++) x += g_lpart[ks][b][i];
        }
        // online logsumexp over raw logits (used only for t>0)
        if (x > m) { s = s * __expf(m - x) + 1.f; m = x; }
        else       { s += __expf(x - m); }
        float v = (i == VOCAB - 1) ? x - 1000.f : x;  // lpf tweak (compare key)
        if (i == VOCAB - 1) g_lastx[b] = x;           // raw value for exact recompute
        if (better(v, i, lv[15], li[15])) {
#pragma unroll
            for (int j = 15; j >= 1; j--) {
                bool cj  = better(v, i, lv[j],     li[j]);
                bool cjm = better(v, i, lv[j - 1], li[j - 1]);
                float nv = cjm ? lv[j - 1] : v;
                int   ni = cjm ? li[j - 1] : i;
                lv[j] = cj ? nv : lv[j];
                li[j] = cj ? ni : li[j];
            }
            bool c0 = better(v, i, lv[0], li[0]);
            if (c0) { lv[0] = v; li[0] = i; }
        }
    }
#pragma unroll
    for (int j = 0; j < 16; j++) { sv[tid][j] = lv[j]; si[tid][j] = li[j]; }
    rm[tid] = m; rs[tid] = s;
    __syncthreads();

    for (int stride = 128; stride >= 1; stride >>= 1) {
        if (tid < stride) {
            float ov[16]; int oi[16];
            merge16(sv[tid], si[tid], sv[tid + stride], si[tid + stride], ov, oi);
#pragma unroll
            for (int j = 0; j < 16; j++) { sv[tid][j] = ov[j]; si[tid][j] = oi[j]; }
            float m2 = rm[tid + stride], s2 = rs[tid + stride];
            float m1 = rm[tid], s1 = rs[tid];
            float M = fmaxf(m1, m2);
            rs[tid] = s1 * __expf(m1 - M) + s2 * __expf(m2 - M);
            rm[tid] = M;
        }
        __syncthreads();
    }
    if (tid < 16) {
        g_cv[b][chunk][tid] = sv[0][tid];
        g_ci[b][chunk][tid] = si[0][tid];
    }
    if (tid == 0) { g_cm[b][chunk] = rm[0]; g_cs[b][chunk] = rs[0]; }
}

// ---------------- stage B: merge chunks + normalize + global select (1 block) ----------------
__global__ void __launch_bounds__(256) merge_select(int t) {
    __shared__ float Av[BEAM][NCHUNK][16];
    __shared__ int   Ai[BEAM][NCHUNK][16];
    __shared__ float Bv[BEAM][NCHUNK / 2][16];
    __shared__ int   Bi[BEAM][NCHUNK / 2][16];
    __shared__ float tv[BEAM][16];
    __shared__ int   ti[BEAM][16];
    __shared__ float lzM[BEAM], lzL[BEAM];
    __shared__ float cand[256];
    __shared__ float selv[16];
    __shared__ int   seli[16];
    __shared__ int   q_s[16], c_s[16];
    __shared__ float r_s[16], p_s[16];
    __shared__ int   oldseq[TSTEPS * BEAM];
    __shared__ float oldlp[TSTEPS * BEAM];
    int tid = threadIdx.x;

    // load chunk lists (flat copy)
    for (int idx = tid; idx < BEAM * NCHUNK * 16; idx += 256) {
        ((float*)Av)[idx] = ((const float*)g_cv)[idx];
        ((int*)Ai)[idx]   = ((const int*)g_ci)[idx];
    }
    // snapshot history
    for (int idx = tid; idx < t * BEAM; idx += 256) {
        oldseq[idx] = ((const int*)g_beam_seq)[idx];
        oldlp[idx]  = ((const float*)g_beam_seq_lp)[idx];
    }
    __syncthreads();

    // level 0: 8 -> 4 lists per beam (64 threads)
    if (tid < BEAM * 4) {
        int b = tid >> 2, j = tid & 3;
        merge16(Av[b][2 * j], Ai[b][2 * j], Av[b][2 * j + 1], Ai[b][2 * j + 1],
                Bv[b][j], Bi[b][j]);
    }
    // logsumexp combine per beam (16 threads, independent of merges)
    if (tid >= 128 && tid < 128 + BEAM) {
        int b = tid - 128;
        float M = g_cm[b][0];
#pragma unroll
        for (int c = 1; c < NCHUNK; c++) M = fmaxf(M, g_cm[b][c]);
        float S = 0.f;
#pragma unroll
        for (int c = 0; c < NCHUNK; c++) S += g_cs[b][c] * __expf(g_cm[b][c] - M);
        lzM[b] = M; lzL[b] = logf(S);
    }
    __syncthreads();
    // level 1: 4 -> 2 (32 threads), write into Av[b][0..1]
    if (tid < BEAM * 2) {
        int b = tid >> 1, j = tid & 1;
        merge16(Bv[b][2 * j], Bi[b][2 * j], Bv[b][2 * j + 1], Bi[b][2 * j + 1],
                Av[b][j], Ai[b][j]);
    }
    __syncthreads();
    // level 2: 2 -> 1 (16 threads), result in Bv[b][0]
    if (tid < BEAM) {
        merge16(Av[tid][0], Ai[tid][0], Av[tid][1], Ai[tid][1], Bv[tid][0], Bi[tid][0]);
    }
    __syncthreads();

    // normalize (match reference rounding: ((x - m) - lse), tweak after)
    if (tid < 256) {
        int b = tid >> 4, j = tid & 15;
        float v = Bv[b][0][j];
        int   i = Bi[b][0][j];
        float outv;
        if (t == 0) {
            outv = v;  // input already log_softmax'd; bitwise-exact
        } else {
            float mm = lzM[b], lse = lzL[b];
            if (i == VOCAB - 1) outv = ((g_lastx[b] - mm) - lse) - 1000.f;
            else                outv = (v - mm) - lse;
        }
        tv[b][j] = outv; ti[b][j] = i;
    }
    __syncthreads();

    // global select among 256 candidates
    {
        int qi = tid >> 4, j = tid & 15;
        float cp = g_beam_lps[qi] + tv[qi][j];
        if (t == 0 && qi != 0) cp = -INFINITY;
        cand[tid] = cp;
    }
    __syncthreads();

    if (tid < 32) {
        for (int r = 0; r < 16; r++) {
            float bv = -INFINITY; int bi = 0x7fffffff;
#pragma unroll
            for (int k2 = 0; k2 < 8; k2++) {
                int idx = tid * 8 + k2;
                float v = cand[idx];
                if (better(v, idx, bv, bi)) { bv = v; bi = idx; }
            }
#pragma unroll
            for (int off = 16; off >= 1; off >>= 1) {
                float ov = __shfl_down_sync(0xffffffffu, bv, off);
                int   oi = __shfl_down_sync(0xffffffffu, bi, off);
                if (better(ov, oi, bv, bi)) { bv = ov; bi = oi; }
            }
            bv = __shfl_sync(0xffffffffu, bv, 0);
            bi = __shfl_sync(0xffffffffu, bi, 0);
            if (tid == 0) { selv[r] = bv; seli[r] = bi; cand[bi] = -INFINITY; }
            __syncwarp();
        }
        if (tid < 16) {
            int fi = seli[tid];
            int q = fi >> 4, col = fi & 15;
            int c = ti[q][col];
            float rr = tv[q][col];
            q_s[tid] = q; c_s[tid] = c; r_s[tid] = rr;
            bool done = (c == 0) || (t == TSTEPS - 1);
            p_s[tid] = done ? -1000.f : selv[tid];
        }
    }
    __syncthreads();

    // history permute + commit
    for (int idx = tid; idx < t * BEAM; idx += 256) {
        int row = idx >> 4, col = idx & 15;
        ((int*)g_beam_seq)[idx]      = oldseq[row * 16 + q_s[col]];
        ((float*)g_beam_seq_lp)[idx] = oldlp[row * 16 + q_s[col]];
    }
    if (tid < 16) {
        g_beam_seq[t][tid]    = c_s[tid];
        g_beam_seq_lp[t][tid] = r_s[tid];
        g_beam_lps[tid]       = p_s[tid];
        g_sel_c[tid] = c_s[tid];
        g_sel_q[tid] = q_s[tid];
    }
}

// ---------------- RNN cell GEMM: concatenated K=2048 ([embed;state] x [Wih;Whh]) ----------------
// grid (8, 64) x 128: cb -> 128 cols, ks -> 32-k chunk (ks<32: Wih/embed, ks>=32: Whh/state)
__global__ void __launch_bounds__(128) gemm1_kernel(const float* __restrict__ embed,
                                                    const float* __restrict__ Wih,
                                                    const float* __restrict__ Whh, int t) {
    const float (*state)[HID] = (t & 1) ? g_stateB : g_stateA;
    int cb = blockIdx.x, ks = blockIdx.y;
    int tid = threadIdx.x;
    int o = cb * 128 + tid;
    bool isHH = ks >= 32;
    const float* W = isHH ? Whh : Wih;
    int k0 = (ks & 31) * 32;

    __shared__ float xs[32][16];   // [kk][beam]
    for (int idx = tid; idx < BEAM * 32; idx += 128) {
        int bb = idx >> 5, kk = idx & 31;
        float xv = isHH ? state[g_sel_q[bb]][k0 + kk]
                        : embed[(size_t)g_sel_c[bb] * HID + k0 + kk];
        xs[kk][bb] = xv;
    }
    __syncthreads();

    unsigned long long acc[8];
#pragma unroll
    for (int p = 0; p < 8; p++) acc[p] = 0ull;
    const float* wp = W + (size_t)k0 * HID + o;
#pragma unroll 8
    for (int kk = 0; kk < 32; kk++) {
        float w = *wp; wp += HID;
        unsigned long long w2 = pack2(w, w);
#pragma unroll
        for (int p = 0; p < 8; p++) {
            unsigned long long x = *(const unsigned long long*)&xs[kk][2 * p];
            fma2(acc[p], x, w2);
        }
    }
#pragma unroll
    for (int p = 0; p < 8; p++) {
        float a, b2; unpack2(acc[p], a, b2);
        g_part1[ks][2 * p][o]     = a;
        g_part1[ks][2 * p + 1][o] = b2;
    }
}

__global__ void reduce_tanh_kernel(const float* __restrict__ bias, int t) {
    float (*out)[HID] = (t & 1) ? g_stateA : g_stateB;
    int i = blockIdx.x * 256 + threadIdx.x;   // 16384 total
    int bb = i >> 10, o = i & 1023;
    float sih = 0.f, shh = 0.f;
#pragma unroll 8
    for (int ks = 0; ks < 32; ks++) sih += g_part1[ks][bb][o];
#pragma unroll 8
    for (int ks = 32; ks < 64; ks++) shh += g_part1[ks][bb][o];
    float pre = (sih + shh) + bias[o];        // matches reference (d1 + d2) + b
    out[bb][o] = tanh_acc(pre);
}

// ---------------- output projection (dominant kernel) ----------------
// grid (125, 8) x 128: 125 col-blocks (256 cols, 2/thread) x 8 k-splits (128 k each)
__global__ void __launch_bounds__(128) gemm2_kernel(const float* __restrict__ Wout, int t) {
    const float (*h)[HID] = (t & 1) ? g_stateA : g_stateB;
    int cb = blockIdx.x, ks = blockIdx.y;
    int tid = threadIdx.x;
    int col = cb * 256 + tid * 2;
    __shared__ float sh[128][18];   // [k][beam], padded
    for (int idx = tid; idx < BEAM * 128; idx += 128) {
        int bb = idx >> 7, kk = idx & 127;
        sh[kk][bb] = h[bb][ks * 128 + kk];
    }
    __syncthreads();
    unsigned long long acc0[8], acc1[8];
#pragma unroll
    for (int p = 0; p < 8; p++) { acc0[p] = 0ull; acc1[p] = 0ull; }
    const float* wp = Wout + (size_t)(ks * 128) * VOCAB + col;
#pragma unroll 8
    for (int kk = 0; kk < 128; kk++) {
        float2 w = *(const float2*)wp; wp += VOCAB;
        unsigned long long w0 = pack2(w.x, w.x);
        unsigned long long w1 = pack2(w.y, w.y);
#pragma unroll
        for (int p = 0; p < 8; p++) {
            unsigned long long x = *(const unsigned long long*)&sh[kk][2 * p];
            fma2(acc0[p], x, w0);
            fma2(acc1[p], x, w1);
        }
    }
#pragma unroll
    for (int p = 0; p < 8; p++) {
        float a, b2;
        unpack2(acc0[p], a, b2);
        g_lpart[ks][2 * p][col]     = a;
        g_lpart[ks][2 * p + 1][col] = b2;
        unpack2(acc1[p], a, b2);
        g_lpart[ks][2 * p][col + 1]     = a;
        g_lpart[ks][2 * p + 1][col + 1] = b2;
    }
}

// ---------------- pack outputs ----------------
__global__ void output_kernel(float* __restrict__ out, int out_size) {
    int i = blockIdx.x * 256 + threadIdx.x;
    if (i >= out_size) return;
    if (i < TSTEPS * BEAM) {
        out[i] = (float)((const int*)g_beam_seq)[i];
    } else if (i < 2 * TSTEPS * BEAM) {
        out[i] = ((const float*)g_beam_seq_lp)[i - TSTEPS * BEAM];
    } else if (i < 2 * TSTEPS * BEAM + BEAM) {
        out[i] = g_beam_lps[i - 2 * TSTEPS * BEAM];
    } else {
        out[i] = 0.f;
    }
}

extern "C" void kernel_launch(void* const* d_in, const int* in_sizes, int n_in,
                              void* d_out, int out_size) {
    const float* state    = (const float*)d_in[0];
    const float* logprobs = (const float*)d_in[1];
    const float* embed    = (const float*)d_in[2];
    const float* W_ih     = (const float*)d_in[3];
    const float* W_hh     = (const float*)d_in[4];
    const float* b        = (const float*)d_in[5];
    const float* W_out    = (const float*)d_in[6];

    init_kernel<<<64, 256>>>(state);
    for (int t = 0; t < TSTEPS; t++) {
        dim3 gs(NCHUNK, BEAM);
        topk_scan<<<gs, 256>>>(logprobs, t);
        merge_select<<<1, 256>>>(t);
        if (t < TSTEPS - 1) {
            dim3 g1(8, KS1);
            gemm1_kernel<<<g1, 128>>>(embed, W_ih, W_hh, t);
            reduce_tanh_kernel<<<64, 256>>>(b, t);
            dim3 g2(125, KS2);
            gemm2_kernel<<<g2, 128>>>(W_out, t);
        }
    }
    int nblk = (out_size + 255) / 256;
    if (nblk < 1) nblk = 1;
    output_kernel<<<nblk, 256>>>((float*)d_out, out_size);
}